// round 15
// baseline (speedup 1.0000x reference)
#include <cuda_runtime.h>
#include <cuda_fp16.h>
#include <cstdint>

#define B_  8
#define C_  512
#define N_  16384
#define IC_ 64
#define SPLITS 32

// ---------------- device scratch (no allocations allowed) ----------------
__device__ __half g_Wqkv[3 * 64 * 512];                       // [192][512] (q,k,v stacked)
__device__ float  g_bias[192];                                // bq|bk|bv
__device__ __half g_QKV[(size_t)3 * 8 * 64 * 16384];          // [qkv][b][64][N]
__device__ float  g_spart[(size_t)SPLITS * 8 * 64 * 64];      // [split][b][i][j]
__device__ __half g_Wcomb[8 * 512 * 64];                      // [b][512][64]

// ---------------- mma.sync m16n8k16 f16 -> f32 ----------------
__device__ __forceinline__ void mma16816(float c[4],
    unsigned a0, unsigned a1, unsigned a2, unsigned a3,
    unsigned b0, unsigned b1)
{
    asm volatile(
        "mma.sync.aligned.m16n8k16.row.col.f32.f16.f16.f32 "
        "{%0,%1,%2,%3},{%4,%5,%6,%7},{%8,%9},{%0,%1,%2,%3};\n"
        : "+f"(c[0]), "+f"(c[1]), "+f"(c[2]), "+f"(c[3])
        : "r"(a0), "r"(a1), "r"(a2), "r"(a3), "r"(b0), "r"(b1));
}

// ---------------- k0: convert QKV weights + biases ----------------
__global__ void k_convw(const float* __restrict__ Wq,
                        const float* __restrict__ Wk,
                        const float* __restrict__ Wv,
                        const float* __restrict__ bq,
                        const float* __restrict__ bk,
                        const float* __restrict__ bv)
{
    int i = blockIdx.x * 256 + threadIdx.x;
    if (i < 64 * 512) {
        g_Wqkv[i]                = __float2half(Wq[i]);
        g_Wqkv[i + 64 * 512]     = __float2half(Wk[i]);
        g_Wqkv[i + 2 * 64 * 512] = __float2half(Wv[i]);
    }
    if (blockIdx.x == 0 && threadIdx.x < 192) {
        int r = threadIdx.x;
        g_bias[r] = (r < 64) ? bq[r] : (r < 128) ? bk[r - 64] : bv[r - 128];
    }
}

// ---------------- k1: fused QKV = Wqkv[192x512] @ x  (one pass over x) ----------------
// Block: 512 threads (16 warps: 4 m-warps x 48 rows, 4 n-warps x 32 cols).
// Output 192 x 128 per block, K = 512 in chunks of 64, register double-buffer.
__global__ __launch_bounds__(512) void k_qkvf(const float* __restrict__ x)
{
    __shared__ __half As[192][66];    // [m][k]
    __shared__ __half Bs[64][132];    // [k][n]

    const int b  = blockIdx.y;
    const int n0 = blockIdx.x * 128;
    const int tid = threadIdx.x, lane = tid & 31, warp = tid >> 5;
    const int wm = warp & 3, wn = warp >> 2;
    const int g = lane >> 2, t = lane & 3;

    const float* xb = x + (size_t)b * C_ * N_ + n0;

    float c[3][4][4];
#pragma unroll
    for (int i = 0; i < 3; i++)
#pragma unroll
        for (int j = 0; j < 4; j++)
#pragma unroll
            for (int k = 0; k < 4; k++) c[i][j][k] = 0.f;

    unsigned aR[12];
    float4   bR[4];

    // prologue: load chunk 0
#pragma unroll
    for (int it = 0; it < 12; it++) {
        int u = tid + it * 512, m = u >> 5, kp = (u & 31) * 2;
        aR[it] = *(const unsigned*)(g_Wqkv + m * 512 + kp);
    }
#pragma unroll
    for (int it = 0; it < 4; it++) {
        int u = tid + it * 512, kk = u >> 5, f = (u & 31) * 4;
        bR[it] = *(const float4*)(xb + (size_t)kk * N_ + f);
    }
#pragma unroll
    for (int it = 0; it < 12; it++) {
        int u = tid + it * 512, m = u >> 5, kp = (u & 31) * 2;
        *(unsigned*)&As[m][kp] = aR[it];
    }
#pragma unroll
    for (int it = 0; it < 4; it++) {
        int u = tid + it * 512, kk = u >> 5, f = (u & 31) * 4;
        __half2 h01 = __floats2half2_rn(bR[it].x, bR[it].y);
        __half2 h23 = __floats2half2_rn(bR[it].z, bR[it].w);
        *(uint2*)&Bs[kk][f] = make_uint2(*(unsigned*)&h01, *(unsigned*)&h23);
    }
    __syncthreads();

    for (int k0 = 0; k0 < 512; k0 += 64) {
        const bool more = (k0 + 64) < 512;
        if (more) {
#pragma unroll
            for (int it = 0; it < 12; it++) {
                int u = tid + it * 512, m = u >> 5, kp = (u & 31) * 2;
                aR[it] = *(const unsigned*)(g_Wqkv + m * 512 + k0 + 64 + kp);
            }
#pragma unroll
            for (int it = 0; it < 4; it++) {
                int u = tid + it * 512, kk = u >> 5, f = (u & 31) * 4;
                bR[it] = *(const float4*)(xb + (size_t)(k0 + 64 + kk) * N_ + f);
            }
        }

#pragma unroll
        for (int ks = 0; ks < 64; ks += 16) {
            unsigned a[3][4];
#pragma unroll
            for (int mf = 0; mf < 3; mf++) {
                int row = wm * 48 + mf * 16 + g;
                const __half* ap = &As[row][ks + t * 2];
                a[mf][0] = *(const unsigned*)(ap);
                a[mf][1] = *(const unsigned*)(ap + 8 * 66);
                a[mf][2] = *(const unsigned*)(ap + 8);
                a[mf][3] = *(const unsigned*)(ap + 8 * 66 + 8);
            }
            const unsigned short* bp = (const unsigned short*)&Bs[0][0];
            const int kb = ks + t * 2;
#pragma unroll
            for (int nf = 0; nf < 4; nf++) {
                int n = wn * 32 + nf * 8 + g;
                unsigned lo0 = bp[(kb) * 132 + n],     hi0 = bp[(kb + 1) * 132 + n];
                unsigned lo1 = bp[(kb + 8) * 132 + n], hi1 = bp[(kb + 9) * 132 + n];
                unsigned b0 = lo0 | (hi0 << 16), b1 = lo1 | (hi1 << 16);
#pragma unroll
                for (int mf = 0; mf < 3; mf++)
                    mma16816(c[mf][nf], a[mf][0], a[mf][1], a[mf][2], a[mf][3], b0, b1);
            }
        }
        __syncthreads();

        if (more) {
#pragma unroll
            for (int it = 0; it < 12; it++) {
                int u = tid + it * 512, m = u >> 5, kp = (u & 31) * 2;
                *(unsigned*)&As[m][kp] = aR[it];
            }
#pragma unroll
            for (int it = 0; it < 4; it++) {
                int u = tid + it * 512, kk = u >> 5, f = (u & 31) * 4;
                __half2 h01 = __floats2half2_rn(bR[it].x, bR[it].y);
                __half2 h23 = __floats2half2_rn(bR[it].z, bR[it].w);
                *(uint2*)&Bs[kk][f] = make_uint2(*(unsigned*)&h01, *(unsigned*)&h23);
            }
            __syncthreads();
        }
    }

    // epilogue: bias + write fp16 QKV (each 16-row frag stays inside one q-block)
#pragma unroll
    for (int mf = 0; mf < 3; mf++) {
        int row = wm * 48 + mf * 16 + g;
        int q = row >> 6, r = row & 63;
        float b0v = g_bias[row], b1v = g_bias[row + 8];
        __half* op = g_QKV + ((size_t)q * 8 + b) * (size_t)64 * N_;
#pragma unroll
        for (int nf = 0; nf < 4; nf++) {
            int col = n0 + wn * 32 + nf * 8 + t * 2;
            *(__half2*)(op + (size_t)r * N_ + col) =
                __floats2half2_rn(c[mf][nf][0] + b0v, c[mf][nf][1] + b0v);
            *(__half2*)(op + (size_t)(r + 8) * N_ + col) =
                __floats2half2_rn(c[mf][nf][2] + b1v, c[mf][nf][3] + b1v);
        }
    }
}

// ---------------- k2: partial scores via HMMA ----------------
// grid (SPLITS, 8), 256 threads (8 warps). Warp w owns j-cols [8w, 8w+8).
__global__ __launch_bounds__(256) void k_scores()
{
    __shared__ __half Qs[64][66];
    __shared__ __half Ks[64][66];
    const int b  = blockIdx.y;
    const int n0 = blockIdx.x * (N_ / SPLITS);   // 512
    const int tid = threadIdx.x, lane = tid & 31, warp = tid >> 5;
    const int g = lane >> 2, t = lane & 3;
    const int jb = warp * 8;

    const __half* Qp = g_QKV + (size_t)b * 64 * N_;
    const __half* Kp = g_QKV + (size_t)(8 + b) * 64 * N_;

    float c[4][4];
#pragma unroll
    for (int i = 0; i < 4; i++)
#pragma unroll
        for (int j = 0; j < 4; j++) c[i][j] = 0.f;

    for (int sc = 0; sc < N_ / SPLITS; sc += 64) {
        const int nb = n0 + sc;
#pragma unroll
        for (int u = tid; u < 2048; u += 256) {
            int m = u >> 5, kp = (u & 31) * 2;
            *(unsigned*)&Qs[m][kp] = *(const unsigned*)(Qp + (size_t)m * N_ + nb + kp);
            *(unsigned*)&Ks[m][kp] = *(const unsigned*)(Kp + (size_t)m * N_ + nb + kp);
        }
        __syncthreads();
#pragma unroll
        for (int ks = 0; ks < 64; ks += 16) {
            unsigned b0 = *(const unsigned*)&Ks[jb + g][ks + t * 2];
            unsigned b1 = *(const unsigned*)&Ks[jb + g][ks + t * 2 + 8];
#pragma unroll
            for (int mf = 0; mf < 4; mf++) {
                const __half* ap = &Qs[mf * 16 + g][ks + t * 2];
                mma16816(c[mf],
                         *(const unsigned*)(ap),
                         *(const unsigned*)(ap + 8 * 66),
                         *(const unsigned*)(ap + 8),
                         *(const unsigned*)(ap + 8 * 66 + 8),
                         b0, b1);
            }
        }
        __syncthreads();
    }

    float* outp = g_spart + ((size_t)blockIdx.x * 8 + b) * 4096;
#pragma unroll
    for (int mf = 0; mf < 4; mf++) {
        int i0 = mf * 16 + g;
        *(float2*)&outp[i0 * 64 + jb + t * 2]       = make_float2(c[mf][0], c[mf][1]);
        *(float2*)&outp[(i0 + 8) * 64 + jb + t * 2] = make_float2(c[mf][2], c[mf][3]);
    }
}

// ---------------- k3: fused reduce + softmax(i) + Wcomb = Wr @ weights ----------------
// grid (8 m-tiles, 8 b), 256 threads. Softmax 1/den folded into the epilogue
// (column scaling commutes with the Wr matmul).
__global__ __launch_bounds__(256) void k_softcomb(const float* __restrict__ Wr)
{
    __shared__ float s[64][65];
    __shared__ float Wrs[64][65];
    __shared__ float colmax[64], colinv[64];
    const int m0 = blockIdx.x * 64, b = blockIdx.y, tid = threadIdx.x;

    for (int u = tid; u < 4096; u += 256) {
        float sum = 0.f;
#pragma unroll
        for (int sp = 0; sp < SPLITS; sp++)
            sum += g_spart[((size_t)sp * 8 + b) * 4096 + u];
        s[u >> 6][u & 63] = sum;
    }
    for (int u = tid; u < 4096; u += 256)
        Wrs[u >> 6][u & 63] = Wr[(m0 + (u >> 6)) * 64 + (u & 63)];
    __syncthreads();

    if (tid < 64) {
        float m = -1e30f;
        for (int i = 0; i < 64; i++) m = fmaxf(m, s[i][tid]);
        colmax[tid] = m;
    }
    __syncthreads();
    for (int u = tid; u < 4096; u += 256) {
        int i = u >> 6, j = u & 63;
        s[i][j] = expf(s[i][j] - colmax[j]);
    }
    __syncthreads();
    if (tid < 64) {
        float d = 0.f;
        for (int i = 0; i < 64; i++) d += s[i][tid];
        colinv[tid] = 1.f / d;
    }
    __syncthreads();

    for (int u = tid; u < 4096; u += 256) {
        int mm = u >> 6, j = u & 63;
        float acc = 0.f;
#pragma unroll
        for (int i = 0; i < 64; i++) acc += Wrs[mm][i] * s[i][j];
        g_Wcomb[((size_t)b * 512 + m0 + mm) * 64 + j] = __float2half(acc * colinv[j]);
    }
}

// ---------------- k4: out = Wcomb[b] @ V + br + x ----------------
__global__ __launch_bounds__(256) void k_out(const float* __restrict__ x,
    const float* __restrict__ br, float* __restrict__ out)
{
    __shared__ __half As[128][66];    // Wcomb rows [m][k]
    __shared__ __half Bs[64][132];    // V [k][n]

    const int b = blockIdx.z, m0 = blockIdx.y * 128, n0 = blockIdx.x * 128;
    const int tid = threadIdx.x, lane = tid & 31, warp = tid >> 5;
    const int wm = warp & 3, wn = warp >> 2;
    const int g = lane >> 2, t = lane & 3;

    const __half* Wc = g_Wcomb + (size_t)b * 512 * 64 + (size_t)m0 * 64;
    const __half* Vp = g_QKV + (size_t)(2 * 8 + b) * 64 * N_;

#pragma unroll
    for (int u = tid; u < 4096; u += 256) {
        int m = u >> 5, kp = (u & 31) * 2;
        *(unsigned*)&As[m][kp] = *(const unsigned*)(Wc + m * 64 + kp);
    }
#pragma unroll
    for (int u = tid; u < 4096; u += 256) {
        int kk = u >> 6, np = (u & 63) * 2;
        *(unsigned*)&Bs[kk][np] = *(const unsigned*)(Vp + (size_t)kk * N_ + n0 + np);
    }
    __syncthreads();

    float c[2][8][4];
#pragma unroll
    for (int i = 0; i < 2; i++)
#pragma unroll
        for (int j = 0; j < 8; j++)
#pragma unroll
            for (int k = 0; k < 4; k++) c[i][j][k] = 0.f;

#pragma unroll
    for (int ks = 0; ks < 64; ks += 16) {
        unsigned a[2][4];
#pragma unroll
        for (int mf = 0; mf < 2; mf++) {
            int row = wm * 32 + mf * 16 + g;
            const __half* ap = &As[row][ks + t * 2];
            a[mf][0] = *(const unsigned*)(ap);
            a[mf][1] = *(const unsigned*)(ap + 8 * 66);
            a[mf][2] = *(const unsigned*)(ap + 8);
            a[mf][3] = *(const unsigned*)(ap + 8 * 66 + 8);
        }
        const unsigned short* bp = (const unsigned short*)&Bs[0][0];
        const int kb = ks + t * 2;
#pragma unroll
        for (int nf = 0; nf < 8; nf++) {
            int n = wn * 64 + nf * 8 + g;
            unsigned lo0 = bp[(kb) * 132 + n],     hi0 = bp[(kb + 1) * 132 + n];
            unsigned lo1 = bp[(kb + 8) * 132 + n], hi1 = bp[(kb + 9) * 132 + n];
            unsigned b0 = lo0 | (hi0 << 16), b1 = lo1 | (hi1 << 16);
#pragma unroll
            for (int mf = 0; mf < 2; mf++)
                mma16816(c[mf][nf], a[mf][0], a[mf][1], a[mf][2], a[mf][3], b0, b1);
        }
    }

    const float* xp = x + (size_t)b * C_ * N_;
    float*       op = out + (size_t)b * C_ * N_;
#pragma unroll
    for (int mf = 0; mf < 2; mf++) {
        int row = m0 + wm * 32 + mf * 16 + g;
        float b0v = br[row], b1v = br[row + 8];
#pragma unroll
        for (int nf = 0; nf < 8; nf++) {
            int col = n0 + wn * 64 + nf * 8 + t * 2;
            float2 xv0 = *(const float2*)(xp + (size_t)row * N_ + col);
            float2 xv1 = *(const float2*)(xp + (size_t)(row + 8) * N_ + col);
            float2 o0, o1;
            o0.x = c[mf][nf][0] + b0v + xv0.x;
            o0.y = c[mf][nf][1] + b0v + xv0.y;
            o1.x = c[mf][nf][2] + b1v + xv1.x;
            o1.y = c[mf][nf][3] + b1v + xv1.y;
            *(float2*)(op + (size_t)row * N_ + col) = o0;
            *(float2*)(op + (size_t)(row + 8) * N_ + col) = o1;
        }
    }
}

// ---------------- launch ----------------
extern "C" void kernel_launch(void* const* d_in, const int* in_sizes, int n_in,
                              void* d_out, int out_size)
{
    const float* x  = (const float*)d_in[0];
    const float* Wq = (const float*)d_in[1];
    const float* bq = (const float*)d_in[2];
    const float* Wk = (const float*)d_in[3];
    const float* bk = (const float*)d_in[4];
    const float* Wv = (const float*)d_in[5];
    const float* bv = (const float*)d_in[6];
    const float* Wr = (const float*)d_in[7];
    const float* br = (const float*)d_in[8];
    float* out = (float*)d_out;

    k_convw<<<128, 256>>>(Wq, Wk, Wv, bq, bk, bv);
    k_qkvf<<<dim3(N_ / 128, B_), 512>>>(x);
    k_scores<<<dim3(SPLITS, B_), 256>>>();
    k_softcomb<<<dim3(8, B_), 256>>>(Wr);
    k_out<<<dim3(N_ / 128, C_ / 128, B_), 256>>>(x, br, out);
}

// round 16
// speedup vs baseline: 1.0072x; 1.0072x over previous
#include <cuda_runtime.h>
#include <cuda_fp16.h>
#include <cstdint>

#define B_  8
#define C_  512
#define N_  16384
#define IC_ 64
#define SPLITS 32

// ---------------- device scratch (no allocations allowed) ----------------
__device__ __half g_Wqkv[3 * 64 * 512];                       // [192][512] (q,k,v stacked)
__device__ float  g_bias[192];                                // bq|bk|bv
__device__ __half g_QKV[(size_t)3 * 8 * 64 * 16384];          // [qkv][b][64][N]
__device__ float  g_spart[(size_t)SPLITS * 8 * 64 * 64];      // [split][b][i][j]
__device__ __half g_Wcomb[8 * 512 * 64];                      // [b][512][64]

// ---------------- mma.sync m16n8k16 f16 -> f32 ----------------
__device__ __forceinline__ void mma16816(float c[4],
    unsigned a0, unsigned a1, unsigned a2, unsigned a3,
    unsigned b0, unsigned b1)
{
    asm volatile(
        "mma.sync.aligned.m16n8k16.row.col.f32.f16.f16.f32 "
        "{%0,%1,%2,%3},{%4,%5,%6,%7},{%8,%9},{%0,%1,%2,%3};\n"
        : "+f"(c[0]), "+f"(c[1]), "+f"(c[2]), "+f"(c[3])
        : "r"(a0), "r"(a1), "r"(a2), "r"(a3), "r"(b0), "r"(b1));
}

// ---------------- k0: convert QKV weights + biases ----------------
__global__ void k_convw(const float* __restrict__ Wq,
                        const float* __restrict__ Wk,
                        const float* __restrict__ Wv,
                        const float* __restrict__ bq,
                        const float* __restrict__ bk,
                        const float* __restrict__ bv)
{
    int i = blockIdx.x * 256 + threadIdx.x;
    if (i < 64 * 512) {
        g_Wqkv[i]                = __float2half(Wq[i]);
        g_Wqkv[i + 64 * 512]     = __float2half(Wk[i]);
        g_Wqkv[i + 2 * 64 * 512] = __float2half(Wv[i]);
    }
    if (blockIdx.x == 0 && threadIdx.x < 192) {
        int r = threadIdx.x;
        g_bias[r] = (r < 64) ? bq[r] : (r < 128) ? bk[r - 64] : bv[r - 128];
    }
}

// ---------------- k1: fused QKV = Wqkv[192x512] @ x  (one pass over x) ----------------
// Block: 512 threads (16 warps: 4 m-warps x 48 rows, 4 n-warps x 32 cols).
// Output 192 x 128 per block, K = 512 in chunks of 64, register double-buffer.
__global__ __launch_bounds__(512) void k_qkvf(const float* __restrict__ x)
{
    __shared__ __half As[192][66];    // [m][k]
    __shared__ __half Bs[64][132];    // [k][n]

    const int b  = blockIdx.y;
    const int n0 = blockIdx.x * 128;
    const int tid = threadIdx.x, lane = tid & 31, warp = tid >> 5;
    const int wm = warp & 3, wn = warp >> 2;
    const int g = lane >> 2, t = lane & 3;

    const float* xb = x + (size_t)b * C_ * N_ + n0;

    float c[3][4][4];
#pragma unroll
    for (int i = 0; i < 3; i++)
#pragma unroll
        for (int j = 0; j < 4; j++)
#pragma unroll
            for (int k = 0; k < 4; k++) c[i][j][k] = 0.f;

    unsigned aR[12];
    float4   bR[4];

    // prologue: load chunk 0
#pragma unroll
    for (int it = 0; it < 12; it++) {
        int u = tid + it * 512, m = u >> 5, kp = (u & 31) * 2;
        aR[it] = *(const unsigned*)(g_Wqkv + m * 512 + kp);
    }
#pragma unroll
    for (int it = 0; it < 4; it++) {
        int u = tid + it * 512, kk = u >> 5, f = (u & 31) * 4;
        bR[it] = *(const float4*)(xb + (size_t)kk * N_ + f);
    }
#pragma unroll
    for (int it = 0; it < 12; it++) {
        int u = tid + it * 512, m = u >> 5, kp = (u & 31) * 2;
        *(unsigned*)&As[m][kp] = aR[it];
    }
#pragma unroll
    for (int it = 0; it < 4; it++) {
        int u = tid + it * 512, kk = u >> 5, f = (u & 31) * 4;
        __half2 h01 = __floats2half2_rn(bR[it].x, bR[it].y);
        __half2 h23 = __floats2half2_rn(bR[it].z, bR[it].w);
        *(uint2*)&Bs[kk][f] = make_uint2(*(unsigned*)&h01, *(unsigned*)&h23);
    }
    __syncthreads();

    for (int k0 = 0; k0 < 512; k0 += 64) {
        const bool more = (k0 + 64) < 512;
        if (more) {
#pragma unroll
            for (int it = 0; it < 12; it++) {
                int u = tid + it * 512, m = u >> 5, kp = (u & 31) * 2;
                aR[it] = *(const unsigned*)(g_Wqkv + m * 512 + k0 + 64 + kp);
            }
#pragma unroll
            for (int it = 0; it < 4; it++) {
                int u = tid + it * 512, kk = u >> 5, f = (u & 31) * 4;
                bR[it] = *(const float4*)(xb + (size_t)(k0 + 64 + kk) * N_ + f);
            }
        }

#pragma unroll
        for (int ks = 0; ks < 64; ks += 16) {
            unsigned a[3][4];
#pragma unroll
            for (int mf = 0; mf < 3; mf++) {
                int row = wm * 48 + mf * 16 + g;
                const __half* ap = &As[row][ks + t * 2];
                a[mf][0] = *(const unsigned*)(ap);
                a[mf][1] = *(const unsigned*)(ap + 8 * 66);
                a[mf][2] = *(const unsigned*)(ap + 8);
                a[mf][3] = *(const unsigned*)(ap + 8 * 66 + 8);
            }
            const unsigned short* bp = (const unsigned short*)&Bs[0][0];
            const int kb = ks + t * 2;
#pragma unroll
            for (int nf = 0; nf < 4; nf++) {
                int n = wn * 32 + nf * 8 + g;
                unsigned lo0 = bp[(kb) * 132 + n],     hi0 = bp[(kb + 1) * 132 + n];
                unsigned lo1 = bp[(kb + 8) * 132 + n], hi1 = bp[(kb + 9) * 132 + n];
                unsigned b0 = lo0 | (hi0 << 16), b1 = lo1 | (hi1 << 16);
#pragma unroll
                for (int mf = 0; mf < 3; mf++)
                    mma16816(c[mf][nf], a[mf][0], a[mf][1], a[mf][2], a[mf][3], b0, b1);
            }
        }
        __syncthreads();

        if (more) {
#pragma unroll
            for (int it = 0; it < 12; it++) {
                int u = tid + it * 512, m = u >> 5, kp = (u & 31) * 2;
                *(unsigned*)&As[m][kp] = aR[it];
            }
#pragma unroll
            for (int it = 0; it < 4; it++) {
                int u = tid + it * 512, kk = u >> 5, f = (u & 31) * 4;
                __half2 h01 = __floats2half2_rn(bR[it].x, bR[it].y);
                __half2 h23 = __floats2half2_rn(bR[it].z, bR[it].w);
                *(uint2*)&Bs[kk][f] = make_uint2(*(unsigned*)&h01, *(unsigned*)&h23);
            }
            __syncthreads();
        }
    }

    // epilogue: bias + write fp16 QKV (each 16-row frag stays inside one q-block)
#pragma unroll
    for (int mf = 0; mf < 3; mf++) {
        int row = wm * 48 + mf * 16 + g;
        int q = row >> 6, r = row & 63;
        float b0v = g_bias[row], b1v = g_bias[row + 8];
        __half* op = g_QKV + ((size_t)q * 8 + b) * (size_t)64 * N_;
#pragma unroll
        for (int nf = 0; nf < 4; nf++) {
            int col = n0 + wn * 32 + nf * 8 + t * 2;
            *(__half2*)(op + (size_t)r * N_ + col) =
                __floats2half2_rn(c[mf][nf][0] + b0v, c[mf][nf][1] + b0v);
            *(__half2*)(op + (size_t)(r + 8) * N_ + col) =
                __floats2half2_rn(c[mf][nf][2] + b1v, c[mf][nf][3] + b1v);
        }
    }
}

// ---------------- k2: partial scores via HMMA ----------------
// grid (SPLITS, 8), 256 threads (8 warps). Warp w owns j-cols [8w, 8w+8).
__global__ __launch_bounds__(256) void k_scores()
{
    __shared__ __half Qs[64][66];
    __shared__ __half Ks[64][66];
    const int b  = blockIdx.y;
    const int n0 = blockIdx.x * (N_ / SPLITS);   // 512
    const int tid = threadIdx.x, lane = tid & 31, warp = tid >> 5;
    const int g = lane >> 2, t = lane & 3;
    const int jb = warp * 8;

    const __half* Qp = g_QKV + (size_t)b * 64 * N_;
    const __half* Kp = g_QKV + (size_t)(8 + b) * 64 * N_;

    float c[4][4];
#pragma unroll
    for (int i = 0; i < 4; i++)
#pragma unroll
        for (int j = 0; j < 4; j++) c[i][j] = 0.f;

    for (int sc = 0; sc < N_ / SPLITS; sc += 64) {
        const int nb = n0 + sc;
#pragma unroll
        for (int u = tid; u < 2048; u += 256) {
            int m = u >> 5, kp = (u & 31) * 2;
            *(unsigned*)&Qs[m][kp] = *(const unsigned*)(Qp + (size_t)m * N_ + nb + kp);
            *(unsigned*)&Ks[m][kp] = *(const unsigned*)(Kp + (size_t)m * N_ + nb + kp);
        }
        __syncthreads();
#pragma unroll
        for (int ks = 0; ks < 64; ks += 16) {
            unsigned b0 = *(const unsigned*)&Ks[jb + g][ks + t * 2];
            unsigned b1 = *(const unsigned*)&Ks[jb + g][ks + t * 2 + 8];
#pragma unroll
            for (int mf = 0; mf < 4; mf++) {
                const __half* ap = &Qs[mf * 16 + g][ks + t * 2];
                mma16816(c[mf],
                         *(const unsigned*)(ap),
                         *(const unsigned*)(ap + 8 * 66),
                         *(const unsigned*)(ap + 8),
                         *(const unsigned*)(ap + 8 * 66 + 8),
                         b0, b1);
            }
        }
        __syncthreads();
    }

    float* outp = g_spart + ((size_t)blockIdx.x * 8 + b) * 4096;
#pragma unroll
    for (int mf = 0; mf < 4; mf++) {
        int i0 = mf * 16 + g;
        *(float2*)&outp[i0 * 64 + jb + t * 2]       = make_float2(c[mf][0], c[mf][1]);
        *(float2*)&outp[(i0 + 8) * 64 + jb + t * 2] = make_float2(c[mf][2], c[mf][3]);
    }
}

// ---------------- k3: fused reduce + softmax(i) + Wcomb = Wr @ weights ----------------
// grid (8 m-tiles, 8 b), 256 threads. Softmax 1/den folded into the epilogue
// (column scaling commutes with the Wr matmul).
__global__ __launch_bounds__(256) void k_softcomb(const float* __restrict__ Wr)
{
    __shared__ float s[64][65];
    __shared__ float Wrs[64][65];
    __shared__ float colmax[64], colinv[64];
    const int m0 = blockIdx.x * 64, b = blockIdx.y, tid = threadIdx.x;

    for (int u = tid; u < 4096; u += 256) {
        float sum = 0.f;
#pragma unroll
        for (int sp = 0; sp < SPLITS; sp++)
            sum += g_spart[((size_t)sp * 8 + b) * 4096 + u];
        s[u >> 6][u & 63] = sum;
    }
    for (int u = tid; u < 4096; u += 256)
        Wrs[u >> 6][u & 63] = Wr[(m0 + (u >> 6)) * 64 + (u & 63)];
    __syncthreads();

    if (tid < 64) {
        float m = -1e30f;
        for (int i = 0; i < 64; i++) m = fmaxf(m, s[i][tid]);
        colmax[tid] = m;
    }
    __syncthreads();
    for (int u = tid; u < 4096; u += 256) {
        int i = u >> 6, j = u & 63;
        s[i][j] = expf(s[i][j] - colmax[j]);
    }
    __syncthreads();
    if (tid < 64) {
        float d = 0.f;
        for (int i = 0; i < 64; i++) d += s[i][tid];
        colinv[tid] = 1.f / d;
    }
    __syncthreads();

    for (int u = tid; u < 4096; u += 256) {
        int mm = u >> 6, j = u & 63;
        float acc = 0.f;
#pragma unroll
        for (int i = 0; i < 64; i++) acc += Wrs[mm][i] * s[i][j];
        g_Wcomb[((size_t)b * 512 + m0 + mm) * 64 + j] = __float2half(acc * colinv[j]);
    }
}

// ---------------- k4: out = Wcomb[b] @ V + br + x ----------------
__global__ __launch_bounds__(256) void k_out(const float* __restrict__ x,
    const float* __restrict__ br, float* __restrict__ out)
{
    __shared__ __half As[128][66];    // Wcomb rows [m][k]
    __shared__ __half Bs[64][132];    // V [k][n]

    const int b = blockIdx.z, m0 = blockIdx.y * 128, n0 = blockIdx.x * 128;
    const int tid = threadIdx.x, lane = tid & 31, warp = tid >> 5;
    const int wm = warp & 3, wn = warp >> 2;
    const int g = lane >> 2, t = lane & 3;

    const __half* Wc = g_Wcomb + (size_t)b * 512 * 64 + (size_t)m0 * 64;
    const __half* Vp = g_QKV + (size_t)(2 * 8 + b) * 64 * N_;

#pragma unroll
    for (int u = tid; u < 4096; u += 256) {
        int m = u >> 5, kp = (u & 31) * 2;
        *(unsigned*)&As[m][kp] = *(const unsigned*)(Wc + m * 64 + kp);
    }
#pragma unroll
    for (int u = tid; u < 4096; u += 256) {
        int kk = u >> 6, np = (u & 63) * 2;
        *(unsigned*)&Bs[kk][np] = *(const unsigned*)(Vp + (size_t)kk * N_ + n0 + np);
    }
    __syncthreads();

    float c[2][8][4];
#pragma unroll
    for (int i = 0; i < 2; i++)
#pragma unroll
        for (int j = 0; j < 8; j++)
#pragma unroll
            for (int k = 0; k < 4; k++) c[i][j][k] = 0.f;

#pragma unroll
    for (int ks = 0; ks < 64; ks += 16) {
        unsigned a[2][4];
#pragma unroll
        for (int mf = 0; mf < 2; mf++) {
            int row = wm * 32 + mf * 16 + g;
            const __half* ap = &As[row][ks + t * 2];
            a[mf][0] = *(const unsigned*)(ap);
            a[mf][1] = *(const unsigned*)(ap + 8 * 66);
            a[mf][2] = *(const unsigned*)(ap + 8);
            a[mf][3] = *(const unsigned*)(ap + 8 * 66 + 8);
        }
        const unsigned short* bp = (const unsigned short*)&Bs[0][0];
        const int kb = ks + t * 2;
#pragma unroll
        for (int nf = 0; nf < 8; nf++) {
            int n = wn * 64 + nf * 8 + g;
            unsigned lo0 = bp[(kb) * 132 + n],     hi0 = bp[(kb + 1) * 132 + n];
            unsigned lo1 = bp[(kb + 8) * 132 + n], hi1 = bp[(kb + 9) * 132 + n];
            unsigned b0 = lo0 | (hi0 << 16), b1 = lo1 | (hi1 << 16);
#pragma unroll
            for (int mf = 0; mf < 2; mf++)
                mma16816(c[mf][nf], a[mf][0], a[mf][1], a[mf][2], a[mf][3], b0, b1);
        }
    }

    const float* xp = x + (size_t)b * C_ * N_;
    float*       op = out + (size_t)b * C_ * N_;
#pragma unroll
    for (int mf = 0; mf < 2; mf++) {
        int row = m0 + wm * 32 + mf * 16 + g;
        float b0v = br[row], b1v = br[row + 8];
#pragma unroll
        for (int nf = 0; nf < 8; nf++) {
            int col = n0 + wn * 64 + nf * 8 + t * 2;
            float2 xv0 = *(const float2*)(xp + (size_t)row * N_ + col);
            float2 xv1 = *(const float2*)(xp + (size_t)(row + 8) * N_ + col);
            float2 o0, o1;
            o0.x = c[mf][nf][0] + b0v + xv0.x;
            o0.y = c[mf][nf][1] + b0v + xv0.y;
            o1.x = c[mf][nf][2] + b1v + xv1.x;
            o1.y = c[mf][nf][3] + b1v + xv1.y;
            *(float2*)(op + (size_t)row * N_ + col) = o0;
            *(float2*)(op + (size_t)(row + 8) * N_ + col) = o1;
        }
    }
}

// ---------------- launch ----------------
extern "C" void kernel_launch(void* const* d_in, const int* in_sizes, int n_in,
                              void* d_out, int out_size)
{
    const float* x  = (const float*)d_in[0];
    const float* Wq = (const float*)d_in[1];
    const float* bq = (const float*)d_in[2];
    const float* Wk = (const float*)d_in[3];
    const float* bk = (const float*)d_in[4];
    const float* Wv = (const float*)d_in[5];
    const float* bv = (const float*)d_in[6];
    const float* Wr = (const float*)d_in[7];
    const float* br = (const float*)d_in[8];
    float* out = (float*)d_out;

    k_convw<<<128, 256>>>(Wq, Wk, Wv, bq, bk, bv);
    k_qkvf<<<dim3(N_ / 128, B_), 512>>>(x);
    k_scores<<<dim3(SPLITS, B_), 256>>>();
    k_softcomb<<<dim3(8, B_), 256>>>(Wr);
    k_out<<<dim3(N_ / 128, C_ / 128, B_), 256>>>(x, br, out);
}